// round 5
// baseline (speedup 1.0000x reference)
#include <cuda_runtime.h>

#define BB 64
#define SS 48
#define EE 512
#define HH 512
#define GG 2048
#define NCTA 128

// ---------------- persistent device scratch (no allocs allowed) ----------------
__device__ float g_gih0[2][SS][BB][GG];   // LN(x @ W_ih0^T), both dirs  (~50MB)
__device__ float g_u[2][BB][GG];          // per-step h @ W_hh^T (raw)
__device__ float g_h[2][BB][HH];
__device__ unsigned g_barcnt = 0;
__device__ unsigned g_excnt = 0;

__device__ __forceinline__ float sigmoidf_(float x) { return 1.0f / (1.0f + expf(-x)); }

// packed f32x2 FMA: acc(2 lanes) += a(2 lanes) * b(2 lanes)   [exact fp32 math]
#define FFMA2(acc, a, b) \
    asm("fma.rn.f32x2 %0, %1, %2, %0;" : "+l"(acc) : "l"(a), "l"(b))

__device__ __forceinline__ float f32x2_sum(unsigned long long v) {
    float lo, hi;
    asm("mov.b64 {%0, %1}, %2;" : "=f"(lo), "=f"(hi) : "l"(v));
    return lo + hi;
}

// persistent dynamic smem layout for the scan kernel
struct ScanSmem {
    float hs[2][64][132];    // double-buffered h tile  (k-pad)
    float ws[2][32][132];    // double-buffered W tile
    float hhg[GG], hhb[GG];  // cached LN_hh params (per dir, per layer)
    float hog[HH], hob[HH];  // cached LN_ho params
    float g1row[GG];         // layer-1 constant input row for this CTA's b
};

// ---------------- grid-wide barrier (all NCTA CTAs co-resident) ----------------
__device__ __forceinline__ void grid_sync(unsigned &target) {
    __syncthreads();
    if (threadIdx.x == 0) {
        __threadfence();                       // release: publish this CTA's stores
        atomicAdd(&g_barcnt, 1u);
        target += NCTA;
        while (*(volatile unsigned*)&g_barcnt < target) { __nanosleep(32); }
        __threadfence();                       // acquire: CCTL.IVALL flushes SM L1D
    }
    __syncthreads();
}

// ---------------- block-wide mean/rstd over (sum, sumsq) contributions ---------
template <int NW>
__device__ __forceinline__ void block_stats(float s, float q, float invN,
                                            float &mu, float &rs) {
    __shared__ float redS[NW], redQ[NW], bc[2];
    int t = threadIdx.x;
    __syncthreads();   // protect shared reuse across calls
#pragma unroll
    for (int o = 16; o > 0; o >>= 1) {
        s += __shfl_xor_sync(0xFFFFFFFFu, s, o);
        q += __shfl_xor_sync(0xFFFFFFFFu, q, o);
    }
    if ((t & 31) == 0) { redS[t >> 5] = s; redQ[t >> 5] = q; }
    __syncthreads();
    if (t == 0) {
        float S = 0.f, Q = 0.f;
#pragma unroll
        for (int i = 0; i < NW; i++) { S += redS[i]; Q += redQ[i]; }
        float m = S * invN;
        bc[0] = m;
        bc[1] = rsqrtf(Q * invN - m * m + 1e-5f);
    }
    __syncthreads();
    mu = bc[0]; rs = bc[1];
}

// ================= Phase A: raw x @ W_ih0^T for all (d, s) =====================
// grid = 2*48*32 = 3072 CTAs; 64b x 64g tile, K = 512, KT = 64.
// Register tile 4b x 4g, FFMA2 k-packed.
__global__ void __launch_bounds__(256, 2) phaseA_gemm(const float* __restrict__ x,
                                                      const float* __restrict__ w_ih0) {
    __shared__ float xs[64][68];
    __shared__ float ws[64][68];
    int r = blockIdx.x;
    int d = r / (SS * 32);
    int rem = r % (SS * 32);
    int s = rem / 32;
    int g0 = (rem % 32) * 64;

    int t = threadIdx.x;
    int tb = t & 15;          // b = tb + 16*i
    int tg = t >> 4;          // g = g0 + 4*tg + j

    unsigned long long acc[4][4];
#pragma unroll
    for (int i = 0; i < 4; i++)
#pragma unroll
        for (int j = 0; j < 4; j++) acc[i][j] = 0ull;

    for (int kt = 0; kt < EE / 64; kt++) {
        int k0 = kt * 64;
#pragma unroll
        for (int i = 0; i < 4; i++) {          // xs: 64x64 = 1024 float4
            int fi = t + 256 * i;
            int b = fi >> 4, kq = fi & 15;
            *(float4*)&xs[b][kq * 4] =
                *(const float4*)(x + ((size_t)b * SS + s) * EE + k0 + kq * 4);
        }
#pragma unroll
        for (int i = 0; i < 4; i++) {          // ws: 64x64 = 1024 float4 (coalesced)
            int fi = t + 256 * i;
            int gg = fi >> 4, kq = fi & 15;
            *(float4*)&ws[gg][kq * 4] =
                *(const float4*)(w_ih0 + ((size_t)d * GG + g0 + gg) * EE + k0 + kq * 4);
        }
        __syncthreads();
#pragma unroll 4
        for (int k = 0; k < 64; k += 4) {
            ulonglong2 wv[4];
#pragma unroll
            for (int j = 0; j < 4; j++)
                wv[j] = *(const ulonglong2*)&ws[4 * tg + j][k];
#pragma unroll
            for (int i = 0; i < 4; i++) {
                ulonglong2 hv = *(const ulonglong2*)&xs[tb + 16 * i][k];
#pragma unroll
                for (int j = 0; j < 4; j++) {
                    FFMA2(acc[i][j], hv.x, wv[j].x);
                    FFMA2(acc[i][j], hv.y, wv[j].y);
                }
            }
        }
        __syncthreads();
    }
#pragma unroll
    for (int i = 0; i < 4; i++) {
        int b = tb + 16 * i;
        float4 o;
        o.x = f32x2_sum(acc[i][0]);
        o.y = f32x2_sum(acc[i][1]);
        o.z = f32x2_sum(acc[i][2]);
        o.w = f32x2_sum(acc[i][3]);
        *(float4*)&g_gih0[d][s][b][g0 + 4 * tg] = o;
    }
}

// ================= Phase A LN (in place, with ln_ih0 params) ===================
__global__ void __launch_bounds__(256) phaseA_ln(const float* __restrict__ gam,
                                                 const float* __restrict__ bet) {
    int r = blockIdx.x;
    int d = r / (SS * BB);
    int rem = r % (SS * BB);
    int s = rem / BB;
    int b = rem % BB;
    float* row = &g_gih0[d][s][b][0];
    int t = threadIdx.x;
    float v[8];
    float sum = 0.f, sq = 0.f;
#pragma unroll
    for (int i = 0; i < 8; i++) {
        v[i] = row[t + 256 * i];
        sum += v[i]; sq += v[i] * v[i];
    }
    float mu, rs;
    block_stats<8>(sum, sq, 1.0f / GG, mu, rs);
    const float* gm = gam + d * GG;
    const float* bt = bet + d * GG;
#pragma unroll
    for (int i = 0; i < 8; i++) {
        int g = t + 256 * i;
        row[g] = (v[i] - mu) * rs * gm[g] + bt[g];
    }
}

// ================= scan GEMM: 64b x 32g tile, K in {512,1024} ==================
// 128 threads; register tile 4b x 4g, FFMA2 k-packed; double-buffered smem.
__device__ void step_gemm(ScanSmem* sm, int d, int chunk, const float* __restrict__ Wd,
                          int K, const float* __restrict__ src0,
                          const float* __restrict__ src1) {
    int t = threadIdx.x;
    int tb = t & 15;              // b = tb + 16*i
    int tg = t >> 4;              // g(local) = 4*tg + j
    int nt = K >> 7;
    const float* Wbase = Wd + (size_t)chunk * 32 * K;

    // prologue: load tile 0
#pragma unroll
    for (int i = 0; i < 16; i++) {
        int fi = t + 128 * i;
        int b = fi >> 5, kq = fi & 31;
        *(float4*)&sm->hs[0][b][kq * 4] = *(const float4*)(src0 + (size_t)b * HH + kq * 4);
    }
#pragma unroll
    for (int i = 0; i < 8; i++) {
        int fi = t + 128 * i;
        int g = fi >> 5, kq = fi & 31;
        *(float4*)&sm->ws[0][g][kq * 4] = *(const float4*)(Wbase + (size_t)g * K + kq * 4);
    }
    __syncthreads();

    unsigned long long acc[4][4];
#pragma unroll
    for (int i = 0; i < 4; i++)
#pragma unroll
        for (int j = 0; j < 4; j++) acc[i][j] = 0ull;

    for (int kt = 0; kt < nt; kt++) {
        int cur = kt & 1;
        if (kt + 1 < nt) {                      // prefetch next tile into other buffer
            int k0 = (kt + 1) << 7;
            const float* src = (k0 < HH) ? (src0 + k0) : (src1 + (k0 - HH));
            int nxt = cur ^ 1;
#pragma unroll
            for (int i = 0; i < 16; i++) {
                int fi = t + 128 * i;
                int b = fi >> 5, kq = fi & 31;
                *(float4*)&sm->hs[nxt][b][kq * 4] =
                    *(const float4*)(src + (size_t)b * HH + kq * 4);
            }
#pragma unroll
            for (int i = 0; i < 8; i++) {
                int fi = t + 128 * i;
                int g = fi >> 5, kq = fi & 31;
                *(float4*)&sm->ws[nxt][g][kq * 4] =
                    *(const float4*)(Wbase + (size_t)g * K + k0 + kq * 4);
            }
        }
#pragma unroll 4
        for (int k = 0; k < 128; k += 4) {
            ulonglong2 wv[4];
#pragma unroll
            for (int j = 0; j < 4; j++)
                wv[j] = *(const ulonglong2*)&sm->ws[cur][4 * tg + j][k];
#pragma unroll
            for (int i = 0; i < 4; i++) {
                ulonglong2 hv = *(const ulonglong2*)&sm->hs[cur][tb + 16 * i][k];
#pragma unroll
                for (int j = 0; j < 4; j++) {
                    FFMA2(acc[i][j], hv.x, wv[j].x);
                    FFMA2(acc[i][j], hv.y, wv[j].y);
                }
            }
        }
        __syncthreads();
    }
#pragma unroll
    for (int i = 0; i < 4; i++) {
        int b = tb + 16 * i;
        float4 o;
        o.x = f32x2_sum(acc[i][0]);
        o.y = f32x2_sum(acc[i][1]);
        o.z = f32x2_sum(acc[i][2]);
        o.w = f32x2_sum(acc[i][3]);
        *(float4*)&g_u[d][b][chunk * 32 + 4 * tg] = o;
    }
}

// ================= pointwise: CTA owns row (d, b); c kept in registers =========
// 128 threads: each owns 16 of the 2048 u elems, 4 of the 512 h/c elems.
__device__ void step_point(ScanSmem* sm, int d, int b, const float* __restrict__ gih,
                           float (&c)[4], float* __restrict__ outrow) {
    int t = threadIdx.x;
    const float* urow = &g_u[d][b][0];
    float uv[16];
    float s = 0.f, q = 0.f;
#pragma unroll
    for (int i = 0; i < 16; i++) {
        uv[i] = urow[t + 128 * i];
        s += uv[i]; q += uv[i] * uv[i];
    }
    float mu, rs;
    block_stats<4>(s, q, 1.0f / GG, mu, rs);

    float cn[4], og[4];
    float cs = 0.f, cq = 0.f;
#pragma unroll
    for (int i = 0; i < 4; i++) {
        int j = t + 128 * i;
        float vi = gih[j]        + (uv[i]      - mu) * rs * sm->hhg[j]        + sm->hhb[j];
        float vf = gih[512 + j]  + (uv[4 + i]  - mu) * rs * sm->hhg[512 + j]  + sm->hhb[512 + j];
        float vo = gih[1024 + j] + (uv[8 + i]  - mu) * rs * sm->hhg[1024 + j] + sm->hhb[1024 + j];
        float vg = gih[1536 + j] + (uv[12 + i] - mu) * rs * sm->hhg[1536 + j] + sm->hhb[1536 + j];
        float ig = sigmoidf_(vi);
        float fg = sigmoidf_(vf);
        og[i] = sigmoidf_(vo);
        float gv = tanhf(vg);
        float cc = fg * c[i] + ig * gv;
        cn[i] = cc;
        cs += cc; cq += cc * cc;
    }
    float muc, rsc;
    block_stats<4>(cs, cq, 1.0f / HH, muc, rsc);
#pragma unroll
    for (int i = 0; i < 4; i++) {
        int j = t + 128 * i;
        float hval = og[i] * tanhf((cn[i] - muc) * rsc * sm->hog[j] + sm->hob[j]);
        c[i] = cn[i];
        g_h[d][b][j] = hval;
        if (outrow) outrow[j] = hval;
    }
}

// layer-1 input LN into persistent smem; zero h for layer 1
__device__ void g1_finalize(ScanSmem* sm, int d, int b, const float* __restrict__ ihg,
                            const float* __restrict__ ihb) {
    int t = threadIdx.x;
    const float* urow = &g_u[d][b][0];
    float uv[16];
    float s = 0.f, q = 0.f;
#pragma unroll
    for (int i = 0; i < 16; i++) {
        uv[i] = urow[t + 128 * i];
        s += uv[i]; q += uv[i] * uv[i];
    }
    float mu, rs;
    block_stats<4>(s, q, 1.0f / GG, mu, rs);
#pragma unroll
    for (int i = 0; i < 16; i++) {
        int g = t + 128 * i;
        sm->g1row[g] = (uv[i] - mu) * rs * ihg[g] + ihb[g];
    }
#pragma unroll
    for (int i = 0; i < 4; i++) g_h[d][b][t + 128 * i] = 0.f;
}

__device__ void load_params(ScanSmem* sm, const float* __restrict__ hhg,
                            const float* __restrict__ hhb, const float* __restrict__ hog,
                            const float* __restrict__ hob) {
    int t = threadIdx.x;
#pragma unroll
    for (int i = 0; i < 16; i++) {
        int j = t + 128 * i;
        sm->hhg[j] = hhg[j];
        sm->hhb[j] = hhb[j];
    }
#pragma unroll
    for (int i = 0; i < 4; i++) {
        int j = t + 128 * i;
        sm->hog[j] = hog[j];
        sm->hob[j] = hob[j];
    }
}

// ================= persistent recurrent kernel ================================
__global__ void __launch_bounds__(128, 1) scan_kernel(
    const float* __restrict__ w_hh0,
    const float* __restrict__ ln_hh0_g, const float* __restrict__ ln_hh0_b,
    const float* __restrict__ ln_ho0_g, const float* __restrict__ ln_ho0_b,
    const float* __restrict__ w_ih1, const float* __restrict__ w_hh1,
    const float* __restrict__ ln_ih1_g, const float* __restrict__ ln_ih1_b,
    const float* __restrict__ ln_hh1_g, const float* __restrict__ ln_hh1_b,
    const float* __restrict__ ln_ho1_g, const float* __restrict__ ln_ho1_b,
    float* __restrict__ out) {
    extern __shared__ float smbuf[];
    ScanSmem* sm = (ScanSmem*)smbuf;

    int r = blockIdx.x;
    int d = r >> 6;       // direction
    int cb = r & 63;      // g-chunk (GEMM role) == b (pointwise role)
    int t = threadIdx.x;
    unsigned target = 0;
    float c[4] = {0.f, 0.f, 0.f, 0.f};

    load_params(sm, ln_hh0_g + d * GG, ln_hh0_b + d * GG,
                ln_ho0_g + d * HH, ln_ho0_b + d * HH);
#pragma unroll
    for (int i = 0; i < 4; i++) g_h[d][cb][t + 128 * i] = 0.f;
    grid_sync(target);

    // ---- layer 0 scan (both directions in parallel across CTAs) ----
    const float* h0 = &g_h[d][0][0];
    for (int st = 0; st < SS; st++) {
        step_gemm(sm, d, cb, w_hh0 + (size_t)d * GG * HH, HH, h0, h0);
        grid_sync(target);
        int te = (d == 0) ? st : (SS - 1 - st);
        step_point(sm, d, cb, &g_gih0[d][te][cb][0], c, nullptr);
        grid_sync(target);
    }

    // ---- layer-1 input: g1 = LN(concat(hf,hb) @ W_ih1^T), cached in smem ----
    step_gemm(sm, d, cb, w_ih1 + (size_t)d * GG * (2 * HH), 2 * HH,
              &g_h[0][0][0], &g_h[1][0][0]);
    grid_sync(target);
    g1_finalize(sm, d, cb, ln_ih1_g + d * GG, ln_ih1_b + d * GG);
#pragma unroll
    for (int i = 0; i < 4; i++) c[i] = 0.f;
    __syncthreads();
    load_params(sm, ln_hh1_g + d * GG, ln_hh1_b + d * GG,
                ln_ho1_g + d * HH, ln_ho1_b + d * HH);
    grid_sync(target);

    // ---- layer 1 scan (time-constant input) ----
    for (int st = 0; st < SS; st++) {
        step_gemm(sm, d, cb, w_hh1 + (size_t)d * GG * HH, HH, h0, h0);
        grid_sync(target);
        bool last = (st == SS - 1);
        step_point(sm, d, cb, sm->g1row, c,
                   last ? (out + (size_t)cb * 1024 + d * 512) : nullptr);
        if (!last) grid_sync(target);
    }

    // ---- exit protocol: last CTA to leave resets barrier counters ----
    __syncthreads();
    if (t == 0) {
        __threadfence();
        unsigned n = atomicAdd(&g_excnt, 1u) + 1;
        if (n == NCTA) {
            g_barcnt = 0;
            g_excnt = 0;
            __threadfence();
        }
    }
}

// =============================================================================
extern "C" void kernel_launch(void* const* d_in, const int* in_sizes, int n_in,
                              void* d_out, int out_size) {
    const float* x        = (const float*)d_in[0];
    // d_in[1] = text_length (unused by the reference forward)
    const float* w_ih0    = (const float*)d_in[2];
    const float* w_hh0    = (const float*)d_in[3];
    const float* ln_ih0_g = (const float*)d_in[4];
    const float* ln_ih0_b = (const float*)d_in[5];
    const float* ln_hh0_g = (const float*)d_in[6];
    const float* ln_hh0_b = (const float*)d_in[7];
    const float* ln_ho0_g = (const float*)d_in[8];
    const float* ln_ho0_b = (const float*)d_in[9];
    const float* w_ih1    = (const float*)d_in[10];
    const float* w_hh1    = (const float*)d_in[11];
    const float* ln_ih1_g = (const float*)d_in[12];
    const float* ln_ih1_b = (const float*)d_in[13];
    const float* ln_hh1_g = (const float*)d_in[14];
    const float* ln_hh1_b = (const float*)d_in[15];
    const float* ln_ho1_g = (const float*)d_in[16];
    const float* ln_ho1_b = (const float*)d_in[17];
    float* out = (float*)d_out;

    static int smem_set = 0;
    if (!smem_set) {
        cudaFuncSetAttribute(scan_kernel, cudaFuncAttributeMaxDynamicSharedMemorySize,
                             (int)sizeof(ScanSmem));
        smem_set = 1;
    }

    phaseA_gemm<<<2 * SS * 32, 256>>>(x, w_ih0);
    phaseA_ln<<<2 * SS * BB, 256>>>(ln_ih0_g, ln_ih0_b);
    scan_kernel<<<NCTA, 128, sizeof(ScanSmem)>>>(
        w_hh0, ln_hh0_g, ln_hh0_b, ln_ho0_g, ln_ho0_b,
        w_ih1, w_hh1, ln_ih1_g, ln_ih1_b,
        ln_hh1_g, ln_hh1_b, ln_ho1_g, ln_ho1_b, out);
}

// round 6
// speedup vs baseline: 1.3812x; 1.3812x over previous
#include <cuda_runtime.h>

#define BB 64
#define SS 48
#define EE 512
#define HH 512
#define GG 2048
#define NCTA 128

// ---------------- persistent device scratch (no allocs allowed) ----------------
__device__ float g_gih0[2][SS][BB][GG];   // LN(x @ W_ih0^T), both dirs  (~50MB)
__device__ float g_u[2][BB][GG];          // per-step h @ W_hh^T (raw)
__device__ float g_h[2][BB][HH];
__device__ unsigned g_barcnt = 0;
__device__ unsigned g_excnt = 0;

__device__ __forceinline__ float sigmoidf_(float x) { return 1.0f / (1.0f + expf(-x)); }

// persistent dynamic smem layout for the scan kernel (~162 KB)
struct ScanSmem {
    float hs[2][64][132];    // double-buffered h tile (k-pad for 16B-aligned rows)
    float ws[32][516];       // RESIDENT W slice for this CTA's 32 g-rows (K=512)
    float hhg[GG], hhb[GG];  // cached LN_hh params (per dir, per layer)
    float hog[HH], hob[HH];  // cached LN_ho params
    float g1row[GG];         // layer-1 constant input row for this CTA's b
};

// ---------------- grid-wide barrier (all NCTA CTAs co-resident) ----------------
__device__ __forceinline__ void grid_sync(unsigned &target) {
    __syncthreads();
    if (threadIdx.x == 0) {
        __threadfence();                       // release: publish this CTA's stores
        atomicAdd(&g_barcnt, 1u);
        target += NCTA;
        while (*(volatile unsigned*)&g_barcnt < target) { __nanosleep(32); }
        __threadfence();                       // acquire: CCTL.IVALL flushes SM L1D
    }
    __syncthreads();
}

// ---------------- block-wide mean/rstd over (sum, sumsq) contributions ---------
__device__ __forceinline__ void block_stats(float s, float q, float invN,
                                            float &mu, float &rs) {
    __shared__ float redS[8], redQ[8], bc[2];
    int t = threadIdx.x;
    __syncthreads();   // protect shared reuse across calls
#pragma unroll
    for (int o = 16; o > 0; o >>= 1) {
        s += __shfl_xor_sync(0xFFFFFFFFu, s, o);
        q += __shfl_xor_sync(0xFFFFFFFFu, q, o);
    }
    if ((t & 31) == 0) { redS[t >> 5] = s; redQ[t >> 5] = q; }
    __syncthreads();
    if (t == 0) {
        float S = 0.f, Q = 0.f;
#pragma unroll
        for (int i = 0; i < 8; i++) { S += redS[i]; Q += redQ[i]; }
        float m = S * invN;
        bc[0] = m;
        bc[1] = rsqrtf(Q * invN - m * m + 1e-5f);
    }
    __syncthreads();
    mu = bc[0]; rs = bc[1];
}

// ================= Phase A: raw x @ W_ih0^T for all (d, s) =====================
// grid = 2*48*32 = 3072 CTAs; 64b x 64g tile, K = 512, KT = 64.  (R4 version —
// measured at the 3-reg FFMA chip floor, 382us.)
__global__ void __launch_bounds__(256, 2) phaseA_gemm(const float* __restrict__ x,
                                                      const float* __restrict__ w_ih0) {
    __shared__ float xs[64][68];
    __shared__ float ws[64][68];
    int r = blockIdx.x;
    int d = r / (SS * 32);
    int rem = r % (SS * 32);
    int s = rem / 32;
    int g0 = (rem % 32) * 64;

    int t = threadIdx.x;
    int tb = t & 15;          // b groups: b = tb + 16*i
    int tg = t >> 4;          // g groups: g = g0 + tg + 16*j

    float acc[4][4];
#pragma unroll
    for (int i = 0; i < 4; i++)
#pragma unroll
        for (int j = 0; j < 4; j++) acc[i][j] = 0.f;

    for (int kt = 0; kt < EE / 64; kt++) {
        int k0 = kt * 64;
#pragma unroll
        for (int i = 0; i < 4; i++) {          // xs: 64x64 = 1024 float4
            int fi = t + 256 * i;
            int b = fi >> 4, kq = fi & 15;
            *(float4*)&xs[b][kq * 4] =
                *(const float4*)(x + ((size_t)b * SS + s) * EE + k0 + kq * 4);
        }
#pragma unroll
        for (int i = 0; i < 4; i++) {          // ws: 64x64 = 1024 float4 (coalesced)
            int fi = t + 256 * i;
            int gg = fi >> 4, kq = fi & 15;
            *(float4*)&ws[gg][kq * 4] =
                *(const float4*)(w_ih0 + ((size_t)d * GG + g0 + gg) * EE + k0 + kq * 4);
        }
        __syncthreads();
#pragma unroll 4
        for (int k = 0; k < 64; k += 4) {
            float4 wv[4];
#pragma unroll
            for (int j = 0; j < 4; j++) wv[j] = *(float4*)&ws[tg + 16 * j][k];
#pragma unroll
            for (int i = 0; i < 4; i++) {
                float4 hv = *(float4*)&xs[tb + 16 * i][k];
#pragma unroll
                for (int j = 0; j < 4; j++) {
                    acc[i][j] += hv.x * wv[j].x + hv.y * wv[j].y
                               + hv.z * wv[j].z + hv.w * wv[j].w;
                }
            }
        }
        __syncthreads();
    }
#pragma unroll
    for (int i = 0; i < 4; i++) {
        int b = tb + 16 * i;
#pragma unroll
        for (int j = 0; j < 4; j++)
            g_gih0[d][s][b][g0 + tg + 16 * j] = acc[i][j];
    }
}

// ================= Phase A LN (in place, with ln_ih0 params) ===================
__global__ void __launch_bounds__(256) phaseA_ln(const float* __restrict__ gam,
                                                 const float* __restrict__ bet) {
    int r = blockIdx.x;
    int d = r / (SS * BB);
    int rem = r % (SS * BB);
    int s = rem / BB;
    int b = rem % BB;
    float* row = &g_gih0[d][s][b][0];
    int t = threadIdx.x;
    float v[8];
    float sum = 0.f, sq = 0.f;
#pragma unroll
    for (int i = 0; i < 8; i++) {
        v[i] = row[t + 256 * i];
        sum += v[i]; sq += v[i] * v[i];
    }
    float mu, rs;
    block_stats(sum, sq, 1.0f / GG, mu, rs);
    const float* gm = gam + d * GG;
    const float* bt = bet + d * GG;
#pragma unroll
    for (int i = 0; i < 8; i++) {
        int g = t + 256 * i;
        row[g] = (v[i] - mu) * rs * gm[g] + bt[g];
    }
}

// ================= scan-kernel building blocks =================================

// load this CTA's 32 W rows (K=512 columns starting at colOff) into resident smem
__device__ __forceinline__ void load_W(ScanSmem* sm, const float* __restrict__ Wbase,
                                       int rowStride, int colOff) {
    int t = threadIdx.x;
#pragma unroll
    for (int i = 0; i < 16; i++) {             // 32 rows x 128 float4 = 4096
        int fi = t + 256 * i;
        int g = fi >> 7, kq = fi & 127;
        *(float4*)&sm->ws[g][kq * 4] =
            *(const float4*)(Wbase + (size_t)g * rowStride + colOff + kq * 4);
    }
}

// core GEMM: acc += (64b x 32g) tile of src[64][512] @ ws^T; ws already resident.
// k processed in groups of 8: 12 LDS issued up front, then 64 independent FFMAs.
__device__ __forceinline__ void gemm_core(ScanSmem* sm, const float* __restrict__ src,
                                          float (&acc)[4][2]) {
    int t = threadIdx.x;
    int tb = t & 15;              // b = tb + 16*i
    int tg = t >> 4;              // g(local) = 2*tg, 2*tg+1

    // prologue: h tile 0
#pragma unroll
    for (int i = 0; i < 8; i++) {
        int fi = t + 256 * i;
        int b = fi >> 5, kq = fi & 31;
        *(float4*)&sm->hs[0][b][kq * 4] = *(const float4*)(src + (size_t)b * HH + kq * 4);
    }
    __syncthreads();

    for (int kt = 0; kt < 4; kt++) {
        int cur = kt & 1;
        if (kt < 3) {                           // prefetch next h tile
            int k0 = (kt + 1) << 7;
            int nxt = cur ^ 1;
#pragma unroll
            for (int i = 0; i < 8; i++) {
                int fi = t + 256 * i;
                int b = fi >> 5, kq = fi & 31;
                *(float4*)&sm->hs[nxt][b][kq * 4] =
                    *(const float4*)(src + (size_t)b * HH + k0 + kq * 4);
            }
        }
        const int kk = kt << 7;
#pragma unroll 4
        for (int k = 0; k < 128; k += 8) {
            float4 w0a = *(const float4*)&sm->ws[2 * tg][kk + k];
            float4 w1a = *(const float4*)&sm->ws[2 * tg + 1][kk + k];
            float4 w0b = *(const float4*)&sm->ws[2 * tg][kk + k + 4];
            float4 w1b = *(const float4*)&sm->ws[2 * tg + 1][kk + k + 4];
            float4 ha[4], hb[4];
#pragma unroll
            for (int i = 0; i < 4; i++) {
                ha[i] = *(const float4*)&sm->hs[cur][tb + 16 * i][k];
                hb[i] = *(const float4*)&sm->hs[cur][tb + 16 * i][k + 4];
            }
#pragma unroll
            for (int i = 0; i < 4; i++) {
                acc[i][0] += ha[i].x * w0a.x + ha[i].y * w0a.y
                           + ha[i].z * w0a.z + ha[i].w * w0a.w;
                acc[i][1] += ha[i].x * w1a.x + ha[i].y * w1a.y
                           + ha[i].z * w1a.z + ha[i].w * w1a.w;
            }
#pragma unroll
            for (int i = 0; i < 4; i++) {
                acc[i][0] += hb[i].x * w0b.x + hb[i].y * w0b.y
                           + hb[i].z * w0b.z + hb[i].w * w0b.w;
                acc[i][1] += hb[i].x * w1b.x + hb[i].y * w1b.y
                           + hb[i].z * w1b.z + hb[i].w * w1b.w;
            }
        }
        __syncthreads();
    }
}

__device__ __forceinline__ void store_u(int d, int chunk, float (&acc)[4][2]) {
    int t = threadIdx.x;
    int tb = t & 15, tg = t >> 4;
#pragma unroll
    for (int i = 0; i < 4; i++) {
        int b = tb + 16 * i;
        *(float2*)&g_u[d][b][chunk * 32 + 2 * tg] = make_float2(acc[i][0], acc[i][1]);
    }
}

// per-step GEMM with resident W (K=512)
__device__ void step_gemm_res(ScanSmem* sm, int d, int chunk, const float* src) {
    float acc[4][2];
#pragma unroll
    for (int i = 0; i < 4; i++) { acc[i][0] = 0.f; acc[i][1] = 0.f; }
    gemm_core(sm, src, acc);
    store_u(d, chunk, acc);
}

// ================= pointwise: CTA owns row (d, b); c kept in registers =========
__device__ void step_point(ScanSmem* sm, int d, int b, const float* __restrict__ gih,
                           float (&c)[2], float* __restrict__ outrow) {
    int t = threadIdx.x;
    const float* urow = &g_u[d][b][0];
    float uv[8];
    float s = 0.f, q = 0.f;
#pragma unroll
    for (int i = 0; i < 8; i++) {
        uv[i] = urow[t + 256 * i];
        s += uv[i]; q += uv[i] * uv[i];
    }
    float mu, rs;
    block_stats(s, q, 1.0f / GG, mu, rs);

    float cn[2], og[2];
    float cs = 0.f, cq = 0.f;
#pragma unroll
    for (int i = 0; i < 2; i++) {
        int j = t + 256 * i;
        float vi = gih[j]        + (uv[0 + i] - mu) * rs * sm->hhg[j]        + sm->hhb[j];
        float vf = gih[512 + j]  + (uv[2 + i] - mu) * rs * sm->hhg[512 + j]  + sm->hhb[512 + j];
        float vo = gih[1024 + j] + (uv[4 + i] - mu) * rs * sm->hhg[1024 + j] + sm->hhb[1024 + j];
        float vg = gih[1536 + j] + (uv[6 + i] - mu) * rs * sm->hhg[1536 + j] + sm->hhb[1536 + j];
        float ig = sigmoidf_(vi);
        float fg = sigmoidf_(vf);
        og[i] = sigmoidf_(vo);
        float gv = tanhf(vg);
        float cc = fg * c[i] + ig * gv;
        cn[i] = cc;
        cs += cc; cq += cc * cc;
    }
    float muc, rsc;
    block_stats(cs, cq, 1.0f / HH, muc, rsc);
#pragma unroll
    for (int i = 0; i < 2; i++) {
        int j = t + 256 * i;
        float hval = og[i] * tanhf((cn[i] - muc) * rsc * sm->hog[j] + sm->hob[j]);
        c[i] = cn[i];
        g_h[d][b][j] = hval;
        if (outrow) outrow[j] = hval;
    }
}

// layer-1 input LN into persistent smem; zero h for layer 1
__device__ void g1_finalize(ScanSmem* sm, int d, int b, const float* __restrict__ ihg,
                            const float* __restrict__ ihb) {
    int t = threadIdx.x;
    const float* urow = &g_u[d][b][0];
    float uv[8];
    float s = 0.f, q = 0.f;
#pragma unroll
    for (int i = 0; i < 8; i++) {
        uv[i] = urow[t + 256 * i];
        s += uv[i]; q += uv[i] * uv[i];
    }
    float mu, rs;
    block_stats(s, q, 1.0f / GG, mu, rs);
#pragma unroll
    for (int i = 0; i < 8; i++) {
        int g = t + 256 * i;
        sm->g1row[g] = (uv[i] - mu) * rs * ihg[g] + ihb[g];
    }
#pragma unroll
    for (int i = 0; i < 2; i++) g_h[d][b][t + 256 * i] = 0.f;
}

__device__ void load_params(ScanSmem* sm, const float* __restrict__ hhg,
                            const float* __restrict__ hhb, const float* __restrict__ hog,
                            const float* __restrict__ hob) {
    int t = threadIdx.x;
#pragma unroll
    for (int i = 0; i < 8; i++) {
        int j = t + 256 * i;
        sm->hhg[j] = hhg[j];
        sm->hhb[j] = hhb[j];
    }
#pragma unroll
    for (int i = 0; i < 2; i++) {
        int j = t + 256 * i;
        sm->hog[j] = hog[j];
        sm->hob[j] = hob[j];
    }
}

// ================= persistent recurrent kernel ================================
__global__ void __launch_bounds__(256, 1) scan_kernel(
    const float* __restrict__ w_hh0,
    const float* __restrict__ ln_hh0_g, const float* __restrict__ ln_hh0_b,
    const float* __restrict__ ln_ho0_g, const float* __restrict__ ln_ho0_b,
    const float* __restrict__ w_ih1, const float* __restrict__ w_hh1,
    const float* __restrict__ ln_ih1_g, const float* __restrict__ ln_ih1_b,
    const float* __restrict__ ln_hh1_g, const float* __restrict__ ln_hh1_b,
    const float* __restrict__ ln_ho1_g, const float* __restrict__ ln_ho1_b,
    float* __restrict__ out) {
    extern __shared__ float smbuf[];
    ScanSmem* sm = (ScanSmem*)smbuf;

    int r = blockIdx.x;
    int d = r >> 6;       // direction
    int cb = r & 63;      // g-chunk (GEMM role) == b (pointwise role)
    int t = threadIdx.x;
    unsigned target = 0;
    float c[2] = {0.f, 0.f};

    load_params(sm, ln_hh0_g + d * GG, ln_hh0_b + d * GG,
                ln_ho0_g + d * HH, ln_ho0_b + d * HH);
    load_W(sm, w_hh0 + ((size_t)d * GG + cb * 32) * HH, HH, 0);   // W resident
#pragma unroll
    for (int i = 0; i < 2; i++) g_h[d][cb][t + 256 * i] = 0.f;
    grid_sync(target);

    // ---- layer 0 scan (both directions in parallel across CTAs) ----
    const float* h0 = &g_h[d][0][0];
    for (int st = 0; st < SS; st++) {
        step_gemm_res(sm, d, cb, h0);
        grid_sync(target);
        int te = (d == 0) ? st : (SS - 1 - st);
        step_point(sm, d, cb, &g_gih0[d][te][cb][0], c, nullptr);
        grid_sync(target);
    }

    // ---- layer-1 input: u = concat(hf,hb) @ W_ih1^T (K=1024, two passes) ----
    {
        float acc[4][2];
#pragma unroll
        for (int i = 0; i < 4; i++) { acc[i][0] = 0.f; acc[i][1] = 0.f; }
        load_W(sm, w_ih1 + ((size_t)d * GG + cb * 32) * (2 * HH), 2 * HH, 0);
        __syncthreads();
        gemm_core(sm, &g_h[0][0][0], acc);
        load_W(sm, w_ih1 + ((size_t)d * GG + cb * 32) * (2 * HH), 2 * HH, HH);
        __syncthreads();
        gemm_core(sm, &g_h[1][0][0], acc);
        store_u(d, cb, acc);
    }
    grid_sync(target);
    g1_finalize(sm, d, cb, ln_ih1_g + d * GG, ln_ih1_b + d * GG);
    c[0] = 0.f; c[1] = 0.f;
    __syncthreads();
    load_params(sm, ln_hh1_g + d * GG, ln_hh1_b + d * GG,
                ln_ho1_g + d * HH, ln_ho1_b + d * HH);
    load_W(sm, w_hh1 + ((size_t)d * GG + cb * 32) * HH, HH, 0);   // layer-1 W resident
    grid_sync(target);

    // ---- layer 1 scan (time-constant input) ----
    for (int st = 0; st < SS; st++) {
        step_gemm_res(sm, d, cb, h0);
        grid_sync(target);
        bool last = (st == SS - 1);
        step_point(sm, d, cb, sm->g1row, c,
                   last ? (out + (size_t)cb * 1024 + d * 512) : nullptr);
        if (!last) grid_sync(target);
    }

    // ---- exit protocol: last CTA to leave resets barrier counters ----
    __syncthreads();
    if (t == 0) {
        __threadfence();
        unsigned n = atomicAdd(&g_excnt, 1u) + 1;
        if (n == NCTA) {
            g_barcnt = 0;
            g_excnt = 0;
            __threadfence();
        }
    }
}

// =============================================================================
extern "C" void kernel_launch(void* const* d_in, const int* in_sizes, int n_in,
                              void* d_out, int out_size) {
    const float* x        = (const float*)d_in[0];
    // d_in[1] = text_length (unused by the reference forward)
    const float* w_ih0    = (const float*)d_in[2];
    const float* w_hh0    = (const float*)d_in[3];
    const float* ln_ih0_g = (const float*)d_in[4];
    const float* ln_ih0_b = (const float*)d_in[5];
    const float* ln_hh0_g = (const float*)d_in[6];
    const float* ln_hh0_b = (const float*)d_in[7];
    const float* ln_ho0_g = (const float*)d_in[8];
    const float* ln_ho0_b = (const float*)d_in[9];
    const float* w_ih1    = (const float*)d_in[10];
    const float* w_hh1    = (const float*)d_in[11];
    const float* ln_ih1_g = (const float*)d_in[12];
    const float* ln_ih1_b = (const float*)d_in[13];
    const float* ln_hh1_g = (const float*)d_in[14];
    const float* ln_hh1_b = (const float*)d_in[15];
    const float* ln_ho1_g = (const float*)d_in[16];
    const float* ln_ho1_b = (const float*)d_in[17];
    float* out = (float*)d_out;

    static int smem_set = 0;
    if (!smem_set) {
        cudaFuncSetAttribute(scan_kernel, cudaFuncAttributeMaxDynamicSharedMemorySize,
                             (int)sizeof(ScanSmem));
        smem_set = 1;
    }

    phaseA_gemm<<<2 * SS * 32, 256>>>(x, w_ih0);
    phaseA_ln<<<2 * SS * BB, 256>>>(ln_ih0_g, ln_ih0_b);
    scan_kernel<<<NCTA, 256, sizeof(ScanSmem)>>>(
        w_hh0, ln_hh0_g, ln_hh0_b, ln_ho0_g, ln_ho0_b,
        w_ih1, w_hh1, ln_ih1_g, ln_ih1_b,
        ln_hh1_g, ln_hh1_b, ln_ho1_g, ln_ho1_b, out);
}

// round 7
// speedup vs baseline: 1.4748x; 1.0678x over previous
#include <cuda_runtime.h>

#define BB 64
#define SS 48
#define EE 512
#define HH 512
#define GG 2048
#define NCTA 128

// ---------------- persistent device scratch (no allocs allowed) ----------------
__device__ float g_gih0[2][SS][BB][GG];   // LN(x @ W_ih0^T), both dirs  (~50MB)
__device__ float g_u[2][BB][GG];          // per-step h @ W_hh^T (raw)
__device__ float g_h[2][BB][HH];
__device__ unsigned g_barcnt = 0;
__device__ unsigned g_excnt = 0;

__device__ __forceinline__ float sigmoidf_(float x) { return 1.0f / (1.0f + expf(-x)); }

// persistent dynamic smem layout for the scan kernel (226.8 KB)
struct ScanSmem {
    float hs[64][516];       // FULLY resident h (or x-half) tile, 16B-aligned rows
    float ws[32][516];       // resident W slice for this CTA's 32 g-rows (K=512)
    float hhg[GG], hhb[GG];  // cached LN_hh params (per dir, per layer)
    float hog[HH], hob[HH];  // cached LN_ho params
    float g1row[GG];         // layer-1 constant input row for this CTA's b
};

// ---------------- grid-wide barrier (all NCTA CTAs co-resident) ----------------
__device__ __forceinline__ void grid_sync(unsigned &target) {
    __syncthreads();
    if (threadIdx.x == 0) {
        __threadfence();                       // release: publish this CTA's stores
        atomicAdd(&g_barcnt, 1u);
        target += NCTA;
        while (*(volatile unsigned*)&g_barcnt < target) { }
        __threadfence();                       // acquire: invalidate stale L1
    }
    __syncthreads();
}

// ---------------- block-wide mean/rstd over (sum, sumsq) contributions ---------
template <int NW>
__device__ __forceinline__ void block_stats(float s, float q, float invN,
                                            float &mu, float &rs) {
    __shared__ float redS[NW], redQ[NW], bc[2];
    int t = threadIdx.x;
    __syncthreads();   // protect shared reuse across calls
#pragma unroll
    for (int o = 16; o > 0; o >>= 1) {
        s += __shfl_xor_sync(0xFFFFFFFFu, s, o);
        q += __shfl_xor_sync(0xFFFFFFFFu, q, o);
    }
    if ((t & 31) == 0) { redS[t >> 5] = s; redQ[t >> 5] = q; }
    __syncthreads();
    if (t == 0) {
        float S = 0.f, Q = 0.f;
#pragma unroll
        for (int i = 0; i < NW; i++) { S += redS[i]; Q += redQ[i]; }
        float m = S * invN;
        bc[0] = m;
        bc[1] = rsqrtf(Q * invN - m * m + 1e-5f);
    }
    __syncthreads();
    mu = bc[0]; rs = bc[1];
}

// ================= Phase A: raw x @ W_ih0^T for all (d, s) =====================
// (R4/R6 version — measured at the 3-reg FFMA chip floor, 381us. Unchanged.)
__global__ void __launch_bounds__(256, 2) phaseA_gemm(const float* __restrict__ x,
                                                      const float* __restrict__ w_ih0) {
    __shared__ float xs[64][68];
    __shared__ float ws[64][68];
    int r = blockIdx.x;
    int d = r / (SS * 32);
    int rem = r % (SS * 32);
    int s = rem / 32;
    int g0 = (rem % 32) * 64;

    int t = threadIdx.x;
    int tb = t & 15;
    int tg = t >> 4;

    float acc[4][4];
#pragma unroll
    for (int i = 0; i < 4; i++)
#pragma unroll
        for (int j = 0; j < 4; j++) acc[i][j] = 0.f;

    for (int kt = 0; kt < EE / 64; kt++) {
        int k0 = kt * 64;
#pragma unroll
        for (int i = 0; i < 4; i++) {
            int fi = t + 256 * i;
            int b = fi >> 4, kq = fi & 15;
            *(float4*)&xs[b][kq * 4] =
                *(const float4*)(x + ((size_t)b * SS + s) * EE + k0 + kq * 4);
        }
#pragma unroll
        for (int i = 0; i < 4; i++) {
            int fi = t + 256 * i;
            int gg = fi >> 4, kq = fi & 15;
            *(float4*)&ws[gg][kq * 4] =
                *(const float4*)(w_ih0 + ((size_t)d * GG + g0 + gg) * EE + k0 + kq * 4);
        }
        __syncthreads();
#pragma unroll 4
        for (int k = 0; k < 64; k += 4) {
            float4 wv[4];
#pragma unroll
            for (int j = 0; j < 4; j++) wv[j] = *(float4*)&ws[tg + 16 * j][k];
#pragma unroll
            for (int i = 0; i < 4; i++) {
                float4 hv = *(float4*)&xs[tb + 16 * i][k];
#pragma unroll
                for (int j = 0; j < 4; j++) {
                    acc[i][j] += hv.x * wv[j].x + hv.y * wv[j].y
                               + hv.z * wv[j].z + hv.w * wv[j].w;
                }
            }
        }
        __syncthreads();
    }
#pragma unroll
    for (int i = 0; i < 4; i++) {
        int b = tb + 16 * i;
#pragma unroll
        for (int j = 0; j < 4; j++)
            g_gih0[d][s][b][g0 + tg + 16 * j] = acc[i][j];
    }
}

// ================= Phase A LN (in place, with ln_ih0 params) ===================
__global__ void __launch_bounds__(256) phaseA_ln(const float* __restrict__ gam,
                                                 const float* __restrict__ bet) {
    int r = blockIdx.x;
    int d = r / (SS * BB);
    int rem = r % (SS * BB);
    int s = rem / BB;
    int b = rem % BB;
    float* row = &g_gih0[d][s][b][0];
    int t = threadIdx.x;
    float v[8];
    float sum = 0.f, sq = 0.f;
#pragma unroll
    for (int i = 0; i < 8; i++) {
        v[i] = row[t + 256 * i];
        sum += v[i]; sq += v[i] * v[i];
    }
    float mu, rs;
    block_stats<8>(sum, sq, 1.0f / GG, mu, rs);
    const float* gm = gam + d * GG;
    const float* bt = bet + d * GG;
#pragma unroll
    for (int i = 0; i < 8; i++) {
        int g = t + 256 * i;
        row[g] = (v[i] - mu) * rs * gm[g] + bt[g];
    }
}

// ================= scan-kernel building blocks (512 threads) ===================

// load this CTA's 32 W rows (512 columns starting at colOff) into resident smem
__device__ __forceinline__ void load_W(ScanSmem* sm, const float* __restrict__ Wbase,
                                       int rowStride, int colOff) {
    int t = threadIdx.x;
#pragma unroll
    for (int i = 0; i < 8; i++) {             // 32 rows x 128 float4 = 4096
        int fi = t + 512 * i;
        int g = fi >> 7, kq = fi & 127;
        *(float4*)&sm->ws[g][kq * 4] =
            *(const float4*)(Wbase + (size_t)g * rowStride + colOff + kq * 4);
    }
}

// load full 64x512 source into resident hs
__device__ __forceinline__ void load_h(ScanSmem* sm, const float* __restrict__ src) {
    int t = threadIdx.x;
#pragma unroll
    for (int i = 0; i < 16; i++) {            // 64 rows x 128 float4 = 8192
        int fi = t + 512 * i;
        int b = fi >> 7, kq = fi & 127;
        *(float4*)&sm->hs[b][kq * 4] =
            *(const float4*)(src + (size_t)b * HH + kq * 4);
    }
}

// K-split FFMA core: warps 0-7 (half 0) do k in [0,256), warps 8-15 do [256,512).
// Thread tile 4b x 2g. acc accumulates across calls (for K=1024 two-pass).
__device__ __forceinline__ void gemm_ffma(ScanSmem* sm, float (&acc)[4][2]) {
    int t = threadIdx.x;
    int half = t >> 8;
    int tl = t & 255;
    int tb = tl & 15;             // b = tb + 16*i
    int tg = tl >> 4;             // g(local) = 2*tg, 2*tg+1
    const int kk0 = half << 8;
#pragma unroll 4
    for (int k = 0; k < 256; k += 8) {
        float4 w0a = *(const float4*)&sm->ws[2 * tg][kk0 + k];
        float4 w1a = *(const float4*)&sm->ws[2 * tg + 1][kk0 + k];
        float4 w0b = *(const float4*)&sm->ws[2 * tg][kk0 + k + 4];
        float4 w1b = *(const float4*)&sm->ws[2 * tg + 1][kk0 + k + 4];
        float4 ha[4], hb[4];
#pragma unroll
        for (int i = 0; i < 4; i++) {
            ha[i] = *(const float4*)&sm->hs[tb + 16 * i][kk0 + k];
            hb[i] = *(const float4*)&sm->hs[tb + 16 * i][kk0 + k + 4];
        }
#pragma unroll
        for (int i = 0; i < 4; i++) {
            acc[i][0] += ha[i].x * w0a.x + ha[i].y * w0a.y
                       + ha[i].z * w0a.z + ha[i].w * w0a.w;
            acc[i][1] += ha[i].x * w1a.x + ha[i].y * w1a.y
                       + ha[i].z * w1a.z + ha[i].w * w1a.w;
        }
#pragma unroll
        for (int i = 0; i < 4; i++) {
            acc[i][0] += hb[i].x * w0b.x + hb[i].y * w0b.y
                       + hb[i].z * w0b.z + hb[i].w * w0b.w;
            acc[i][1] += hb[i].x * w1b.x + hb[i].y * w1b.y
                       + hb[i].z * w1b.z + hb[i].w * w1b.w;
        }
    }
}

// combine the two K-halves via smem scratch (reuses hs) and store u
__device__ __forceinline__ void reduce_store_u(ScanSmem* sm, int d, int chunk,
                                               float (&acc)[4][2]) {
    int t = threadIdx.x;
    int half = t >> 8;
    int tl = t & 255;
    int tb = tl & 15, tg = tl >> 4;
    float* scratch = &sm->hs[0][0];           // h no longer needed this step
    __syncthreads();                          // all FFMAs done; hs reusable
    if (half == 1) {
#pragma unroll
        for (int i = 0; i < 4; i++) {
            int b = tb + 16 * i;
            scratch[(2 * tg) * 64 + b]     = acc[i][0];
            scratch[(2 * tg + 1) * 64 + b] = acc[i][1];
        }
    }
    __syncthreads();
    if (half == 0) {
#pragma unroll
        for (int i = 0; i < 4; i++) {
            int b = tb + 16 * i;
            float2 o;
            o.x = acc[i][0] + scratch[(2 * tg) * 64 + b];
            o.y = acc[i][1] + scratch[(2 * tg + 1) * 64 + b];
            *(float2*)&g_u[d][b][chunk * 32 + 2 * tg] = o;
        }
    }
}

// per-step GEMM: load h, K-split FFMA, reduce, store
__device__ void step_gemm(ScanSmem* sm, int d, int chunk, const float* src) {
    load_h(sm, src);
    __syncthreads();
    float acc[4][2];
#pragma unroll
    for (int i = 0; i < 4; i++) { acc[i][0] = 0.f; acc[i][1] = 0.f; }
    gemm_ffma(sm, acc);
    reduce_store_u(sm, d, chunk, acc);
}

// ================= pointwise: CTA owns row (d, b); 1 hidden unit per thread ====
// gihr: prefetched gih values (layer 0) or loaded from sm->g1row when useG1.
__device__ void step_point(ScanSmem* sm, int d, int b, const float* gihr, bool useG1,
                           float &c, float* __restrict__ outrow) {
    int j = threadIdx.x;                      // 0..511
    const float* urow = &g_u[d][b][0];
    float uv[4], gv4[4];
    float s = 0.f, q = 0.f;
#pragma unroll
    for (int m = 0; m < 4; m++) {
        uv[m] = urow[j + 512 * m];
        s += uv[m]; q += uv[m] * uv[m];
        gv4[m] = useG1 ? sm->g1row[j + 512 * m] : gihr[m];
    }
    float mu, rs;
    block_stats<16>(s, q, 1.0f / GG, mu, rs);

    float vi = gv4[0] + (uv[0] - mu) * rs * sm->hhg[j]        + sm->hhb[j];
    float vf = gv4[1] + (uv[1] - mu) * rs * sm->hhg[512 + j]  + sm->hhb[512 + j];
    float vo = gv4[2] + (uv[2] - mu) * rs * sm->hhg[1024 + j] + sm->hhb[1024 + j];
    float vg = gv4[3] + (uv[3] - mu) * rs * sm->hhg[1536 + j] + sm->hhb[1536 + j];
    float ig = sigmoidf_(vi);
    float fg = sigmoidf_(vf);
    float og = sigmoidf_(vo);
    float gg = tanhf(vg);
    float cn = fg * c + ig * gg;

    float muc, rsc;
    block_stats<16>(cn, cn * cn, 1.0f / HH, muc, rsc);
    float hval = og * tanhf((cn - muc) * rsc * sm->hog[j] + sm->hob[j]);
    c = cn;
    g_h[d][b][j] = hval;
    if (outrow) outrow[j] = hval;
}

// layer-1 input LN into persistent smem; zero h for layer 1
__device__ void g1_finalize(ScanSmem* sm, int d, int b, const float* __restrict__ ihg,
                            const float* __restrict__ ihb) {
    int t = threadIdx.x;
    const float* urow = &g_u[d][b][0];
    float uv[4];
    float s = 0.f, q = 0.f;
#pragma unroll
    for (int m = 0; m < 4; m++) {
        uv[m] = urow[t + 512 * m];
        s += uv[m]; q += uv[m] * uv[m];
    }
    float mu, rs;
    block_stats<16>(s, q, 1.0f / GG, mu, rs);
#pragma unroll
    for (int m = 0; m < 4; m++) {
        int g = t + 512 * m;
        sm->g1row[g] = (uv[m] - mu) * rs * ihg[g] + ihb[g];
    }
    g_h[d][b][t] = 0.f;
}

__device__ void load_params(ScanSmem* sm, const float* __restrict__ hhg,
                            const float* __restrict__ hhb, const float* __restrict__ hog,
                            const float* __restrict__ hob) {
    int t = threadIdx.x;
#pragma unroll
    for (int i = 0; i < 4; i++) {
        int j = t + 512 * i;
        sm->hhg[j] = hhg[j];
        sm->hhb[j] = hhb[j];
    }
    sm->hog[t] = hog[t];
    sm->hob[t] = hob[t];
}

// ================= persistent recurrent kernel ================================
__global__ void __launch_bounds__(512, 1) scan_kernel(
    const float* __restrict__ w_hh0,
    const float* __restrict__ ln_hh0_g, const float* __restrict__ ln_hh0_b,
    const float* __restrict__ ln_ho0_g, const float* __restrict__ ln_ho0_b,
    const float* __restrict__ w_ih1, const float* __restrict__ w_hh1,
    const float* __restrict__ ln_ih1_g, const float* __restrict__ ln_ih1_b,
    const float* __restrict__ ln_hh1_g, const float* __restrict__ ln_hh1_b,
    const float* __restrict__ ln_ho1_g, const float* __restrict__ ln_ho1_b,
    float* __restrict__ out) {
    extern __shared__ float smbuf[];
    ScanSmem* sm = (ScanSmem*)smbuf;

    int r = blockIdx.x;
    int d = r >> 6;       // direction
    int cb = r & 63;      // g-chunk (GEMM role) == b (pointwise role)
    int t = threadIdx.x;
    unsigned target = 0;
    float c = 0.f;

    load_params(sm, ln_hh0_g + d * GG, ln_hh0_b + d * GG,
                ln_ho0_g + d * HH, ln_ho0_b + d * HH);
    load_W(sm, w_hh0 + ((size_t)d * GG + cb * 32) * HH, HH, 0);   // W resident
    g_h[d][cb][t] = 0.f;
    grid_sync(target);

    // ---- layer 0 scan (both directions in parallel across CTAs) ----
    const float* h0 = &g_h[d][0][0];
    for (int st = 0; st < SS; st++) {
        int te = (d == 0) ? st : (SS - 1 - st);
        const float* gptr = &g_gih0[d][te][cb][0];
        float gihr[4];                     // prefetch gih early: hidden by GEMM
#pragma unroll
        for (int m = 0; m < 4; m++) gihr[m] = gptr[t + 512 * m];
        step_gemm(sm, d, cb, h0);
        grid_sync(target);
        step_point(sm, d, cb, gihr, false, c, nullptr);
        grid_sync(target);
    }

    // ---- layer-1 input: u = concat(hf,hb) @ W_ih1^T (K=1024, two passes) ----
    {
        float acc[4][2];
#pragma unroll
        for (int i = 0; i < 4; i++) { acc[i][0] = 0.f; acc[i][1] = 0.f; }
        load_W(sm, w_ih1 + ((size_t)d * GG + cb * 32) * (2 * HH), 2 * HH, 0);
        load_h(sm, &g_h[0][0][0]);
        __syncthreads();
        gemm_ffma(sm, acc);
        __syncthreads();
        load_W(sm, w_ih1 + ((size_t)d * GG + cb * 32) * (2 * HH), 2 * HH, HH);
        load_h(sm, &g_h[1][0][0]);
        __syncthreads();
        gemm_ffma(sm, acc);
        reduce_store_u(sm, d, cb, acc);
    }
    grid_sync(target);
    g1_finalize(sm, d, cb, ln_ih1_g + d * GG, ln_ih1_b + d * GG);
    c = 0.f;
    __syncthreads();
    load_params(sm, ln_hh1_g + d * GG, ln_hh1_b + d * GG,
                ln_ho1_g + d * HH, ln_ho1_b + d * HH);
    load_W(sm, w_hh1 + ((size_t)d * GG + cb * 32) * HH, HH, 0);   // layer-1 W resident
    grid_sync(target);

    // ---- layer 1 scan (time-constant input in sm->g1row) ----
    for (int st = 0; st < SS; st++) {
        step_gemm(sm, d, cb, h0);
        grid_sync(target);
        bool last = (st == SS - 1);
        step_point(sm, d, cb, nullptr, true, c,
                   last ? (out + (size_t)cb * 1024 + d * 512) : nullptr);
        if (!last) grid_sync(target);
    }

    // ---- exit protocol: last CTA to leave resets barrier counters ----
    __syncthreads();
    if (t == 0) {
        __threadfence();
        unsigned n = atomicAdd(&g_excnt, 1u) + 1;
        if (n == NCTA) {
            g_barcnt = 0;
            g_excnt = 0;
            __threadfence();
        }
    }
}

// =============================================================================
extern "C" void kernel_launch(void* const* d_in, const int* in_sizes, int n_in,
                              void* d_out, int out_size) {
    const float* x        = (const float*)d_in[0];
    // d_in[1] = text_length (unused by the reference forward)
    const float* w_ih0    = (const float*)d_in[2];
    const float* w_hh0    = (const float*)d_in[3];
    const float* ln_ih0_g = (const float*)d_in[4];
    const float* ln_ih0_b = (const float*)d_in[5];
    const float* ln_hh0_g = (const float*)d_in[6];
    const float* ln_hh0_b = (const float*)d_in[7];
    const float* ln_ho0_g = (const float*)d_in[8];
    const float* ln_ho0_b = (const float*)d_in[9];
    const float* w_ih1    = (const float*)d_in[10];
    const float* w_hh1    = (const float*)d_in[11];
    const float* ln_ih1_g = (const float*)d_in[12];
    const float* ln_ih1_b = (const float*)d_in[13];
    const float* ln_hh1_g = (const float*)d_in[14];
    const float* ln_hh1_b = (const float*)d_in[15];
    const float* ln_ho1_g = (const float*)d_in[16];
    const float* ln_ho1_b = (const float*)d_in[17];
    float* out = (float*)d_out;

    static int smem_set = 0;
    if (!smem_set) {
        cudaFuncSetAttribute(scan_kernel, cudaFuncAttributeMaxDynamicSharedMemorySize,
                             (int)sizeof(ScanSmem));
        smem_set = 1;
    }

    phaseA_gemm<<<2 * SS * 32, 256>>>(x, w_ih0);
    phaseA_ln<<<2 * SS * BB, 256>>>(ln_ih0_g, ln_ih0_b);
    scan_kernel<<<NCTA, 512, sizeof(ScanSmem)>>>(
        w_hh0, ln_hh0_g, ln_hh0_b, ln_ho0_g, ln_ho0_b,
        w_ih1, w_hh1, ln_ih1_g, ln_ih1_b,
        ln_hh1_g, ln_hh1_b, ln_ho1_g, ln_ho1_b, out);
}

// round 11
// speedup vs baseline: 2.0306x; 1.3768x over previous
#include <cuda_runtime.h>
#include <cuda_bf16.h>
#include <cstdint>

#define BB 64
#define SS 48
#define EE 512
#define HH 512
#define GG 2048
#define NCTA 128

// ---------------- persistent device scratch (no allocs allowed) ----------------
__device__ float g_gih0[2][SS][BB][GG];   // LN(x @ W_ih0^T), both dirs  (~50MB)
__device__ float g_u[2][BB][GG];          // per-step h @ W_hh^T (raw)
__device__ float g_h[2][BB][HH];
__device__ __nv_bfloat16 g_hbf[2][3][BB][HH];  // [dir][hi/mid/lo] bf16 3-way split of h
__device__ unsigned g_barcnt = 0;
__device__ unsigned g_excnt = 0;

__device__ __forceinline__ float sigmoidf_(float x) { return 1.0f / (1.0f + expf(-x)); }

__device__ __forceinline__ uint32_t smem_u32(const void* p) {
    uint32_t a;
    asm("{ .reg .u64 t; cvta.to.shared.u64 t, %1; cvt.u32.u64 %0, t; }" : "=r"(a) : "l"(p));
    return a;
}

// ---------------- mma.sync helpers (baseline PTX; valid on sm_103) -------------
__device__ __forceinline__ void ldm_x4(uint32_t (&r)[4], uint32_t addr) {
    asm volatile("ldmatrix.sync.aligned.m8n8.x4.shared.b16 {%0,%1,%2,%3}, [%4];"
                 : "=r"(r[0]), "=r"(r[1]), "=r"(r[2]), "=r"(r[3]) : "r"(addr));
}
__device__ __forceinline__ void mma_bf16(float (&c)[4], const uint32_t (&a)[4],
                                         uint32_t b0, uint32_t b1) {
    asm volatile(
        "mma.sync.aligned.m16n8k16.row.col.f32.bf16.bf16.f32 "
        "{%0,%1,%2,%3}, {%4,%5,%6,%7}, {%8,%9}, {%0,%1,%2,%3};"
        : "+f"(c[0]), "+f"(c[1]), "+f"(c[2]), "+f"(c[3])
        : "r"(a[0]), "r"(a[1]), "r"(a[2]), "r"(a[3]), "r"(b0), "r"(b1));
}

// ---------------- grid-wide barrier (all NCTA CTAs co-resident) ----------------
__device__ __forceinline__ void grid_sync(unsigned &target) {
    __syncthreads();
    if (threadIdx.x == 0) {
        __threadfence();
        atomicAdd(&g_barcnt, 1u);
        target += NCTA;
        while (*(volatile unsigned*)&g_barcnt < target) { }
        __threadfence();
    }
    __syncthreads();
}

// ---------------- block stats: static-shared version (phaseA kernels) ----------
template <int NW>
__device__ __forceinline__ void block_stats(float s, float q, float invN,
                                            float &mu, float &rs) {
    __shared__ float redS[NW], redQ[NW], bc[2];
    int t = threadIdx.x;
    __syncthreads();
#pragma unroll
    for (int o = 16; o > 0; o >>= 1) {
        s += __shfl_xor_sync(0xFFFFFFFFu, s, o);
        q += __shfl_xor_sync(0xFFFFFFFFu, q, o);
    }
    if ((t & 31) == 0) { redS[t >> 5] = s; redQ[t >> 5] = q; }
    __syncthreads();
    if (t == 0) {
        float S = 0.f, Q = 0.f;
#pragma unroll
        for (int i = 0; i < NW; i++) { S += redS[i]; Q += redQ[i]; }
        float m = S * invN;
        bc[0] = m;
        bc[1] = rsqrtf(Q * invN - m * m + 1e-5f);
    }
    __syncthreads();
    mu = bc[0]; rs = bc[1];
}

// dynamic-scratch version for the scan kernel (512 threads = 16 warps)
__device__ __forceinline__ void block_stats_d(float s, float q, float invN,
                                              float &mu, float &rs, float* red) {
    int t = threadIdx.x;
    __syncthreads();
#pragma unroll
    for (int o = 16; o > 0; o >>= 1) {
        s += __shfl_xor_sync(0xFFFFFFFFu, s, o);
        q += __shfl_xor_sync(0xFFFFFFFFu, q, o);
    }
    if ((t & 31) == 0) { red[t >> 5] = s; red[16 + (t >> 5)] = q; }
    __syncthreads();
    if (t == 0) {
        float S = 0.f, Q = 0.f;
#pragma unroll
        for (int i = 0; i < 16; i++) { S += red[i]; Q += red[16 + i]; }
        float m = S * invN;
        red[32] = m;
        red[33] = rsqrtf(Q * invN - m * m + 1e-5f);
    }
    __syncthreads();
    mu = red[32]; rs = red[33];
}

// ================= Phase A: raw x @ W_ih0^T (unchanged; at FFMA floor) =========
__global__ void __launch_bounds__(256, 2) phaseA_gemm(const float* __restrict__ x,
                                                      const float* __restrict__ w_ih0) {
    __shared__ float xs[64][68];
    __shared__ float ws[64][68];
    int r = blockIdx.x;
    int d = r / (SS * 32);
    int rem = r % (SS * 32);
    int s = rem / 32;
    int g0 = (rem % 32) * 64;

    int t = threadIdx.x;
    int tb = t & 15;
    int tg = t >> 4;

    float acc[4][4];
#pragma unroll
    for (int i = 0; i < 4; i++)
#pragma unroll
        for (int j = 0; j < 4; j++) acc[i][j] = 0.f;

    for (int kt = 0; kt < EE / 64; kt++) {
        int k0 = kt * 64;
#pragma unroll
        for (int i = 0; i < 4; i++) {
            int fi = t + 256 * i;
            int b = fi >> 4, kq = fi & 15;
            *(float4*)&xs[b][kq * 4] =
                *(const float4*)(x + ((size_t)b * SS + s) * EE + k0 + kq * 4);
        }
#pragma unroll
        for (int i = 0; i < 4; i++) {
            int fi = t + 256 * i;
            int gg = fi >> 4, kq = fi & 15;
            *(float4*)&ws[gg][kq * 4] =
                *(const float4*)(w_ih0 + ((size_t)d * GG + g0 + gg) * EE + k0 + kq * 4);
        }
        __syncthreads();
#pragma unroll 4
        for (int k = 0; k < 64; k += 4) {
            float4 wv[4];
#pragma unroll
            for (int j = 0; j < 4; j++) wv[j] = *(float4*)&ws[tg + 16 * j][k];
#pragma unroll
            for (int i = 0; i < 4; i++) {
                float4 hv = *(float4*)&xs[tb + 16 * i][k];
#pragma unroll
                for (int j = 0; j < 4; j++) {
                    acc[i][j] += hv.x * wv[j].x + hv.y * wv[j].y
                               + hv.z * wv[j].z + hv.w * wv[j].w;
                }
            }
        }
        __syncthreads();
    }
#pragma unroll
    for (int i = 0; i < 4; i++) {
        int b = tb + 16 * i;
#pragma unroll
        for (int j = 0; j < 4; j++)
            g_gih0[d][s][b][g0 + tg + 16 * j] = acc[i][j];
    }
}

// ================= Phase A LN (unchanged) ======================================
__global__ void __launch_bounds__(256) phaseA_ln(const float* __restrict__ gam,
                                                 const float* __restrict__ bet) {
    int r = blockIdx.x;
    int d = r / (SS * BB);
    int rem = r % (SS * BB);
    int s = rem / BB;
    int b = rem % BB;
    float* row = &g_gih0[d][s][b][0];
    int t = threadIdx.x;
    float v[8];
    float sum = 0.f, sq = 0.f;
#pragma unroll
    for (int i = 0; i < 8; i++) {
        v[i] = row[t + 256 * i];
        sum += v[i]; sq += v[i] * v[i];
    }
    float mu, rs;
    block_stats<8>(sum, sq, 1.0f / GG, mu, rs);
    const float* gm = gam + d * GG;
    const float* bt = bet + d * GG;
#pragma unroll
    for (int i = 0; i < 8; i++) {
        int g = t + 256 * i;
        row[g] = (v[i] - mu) * rs * gm[g] + bt[g];
    }
}

// ================= scan-kernel smem layout (byte offsets into dynbuf) ==========
// scan phase:
//   0        : red scratch (136B) + pad                       (256 B)
//   A_OFF    : one h-split tile [64][520] bf16 (66,560 B),
//              also K-reduction scratch [8][64][36] f32 (73,728 B)  -> 73,728
//   W_OFF    : 3 W splits [32][520] bf16 each (3 x 33,280 = 99,840 B)
//   P_OFF    : hhg(8K) hhb(8K) hog(2K) hob(2K) g1row(8K)      (28,672 B)
// concat-GEMM phase (overlays A/W regions):
//   A_OFF    : fp32 hsf[64][516] (132,096 B)
//   CW_OFF   : fp32 wsf[32][516] (66,048 B)   ends at P_OFF
#define A_OFF 256
#define AREG_B 73728
#define W_OFF (A_OFF + AREG_B)
#define WSPL_B 33280
#define CW_OFF (A_OFF + 132096)
#define P_OFF 198400
#define SCAN_SMEM_BYTES (P_OFF + 28672)

// convert this CTA's 32 W rows (fp32, K=512) into bf16 hi/mid/lo padded tiles
__device__ void loadW_bf16(unsigned char* dyn, const float* __restrict__ Wg) {
    int t = threadIdx.x;
    __nv_bfloat16* w0 = (__nv_bfloat16*)(dyn + W_OFF);
    __nv_bfloat16* w1 = (__nv_bfloat16*)(dyn + W_OFF + WSPL_B);
    __nv_bfloat16* w2 = (__nv_bfloat16*)(dyn + W_OFF + 2 * WSPL_B);
#pragma unroll
    for (int i = 0; i < 32; i++) {
        int idx = t + 512 * i;            // g = idx>>9, k = idx&511
        int g = idx >> 9, k = idx & 511;
        float v = Wg[(size_t)g * HH + k];
        __nv_bfloat16 hi = __float2bfloat16(v);
        float r1 = v - __bfloat162float(hi);
        __nv_bfloat16 mid = __float2bfloat16(r1);
        float r2 = r1 - __bfloat162float(mid);
        w0[g * 520 + k] = hi;
        w1[g * 520 + k] = mid;
        w2[g * 520 + k] = __float2bfloat16(r2);
    }
}

// ================= tensor-core step GEMM (mma.sync, 6-term bf16 3-way split) ===
// u[d][b=0..63][cb*32..+32) = h[64][512] @ W[32][512]^T
__device__ void step_gemm_mma(int d, int cb, unsigned char* dyn, uint32_t base_u) {
    int t = threadIdx.x;
    int lane = t & 31, w = t >> 5;
    int mh = w >> 3, ks = w & 7;
    int q = lane >> 3, rr = lane & 7;
    int gid = lane >> 2, tid2 = lane & 3;
    uint32_t hs_u = base_u + A_OFF;
    uint32_t ws_u = base_u + W_OFF;

    float c[2][4][4];
#pragma unroll
    for (int mi = 0; mi < 2; mi++)
#pragma unroll
        for (int nj = 0; nj < 4; nj++)
#pragma unroll
            for (int e = 0; e < 4; e++) c[mi][nj][e] = 0.f;

    int arow = mh * 32 + (q & 1) * 8 + rr;   // + mi*16
    int acol = (q >> 1) * 8;
    int brow = (q >> 1) * 8 + rr;            // + njp*16
    int bcol = (q & 1) * 8;

    // passes: A = h split p; B terms = W splits 0 .. (2-p)
#pragma unroll
    for (int p = 0; p < 3; p++) {
        __syncthreads();                      // prior pass mma reads done before overwrite
        {   // fill h split p: 64 rows x 512 bf16 = 4096 float4
            const float4* src = (const float4*)&g_hbf[d][p][0][0];
            __nv_bfloat16* hdst = (__nv_bfloat16*)(dyn + A_OFF);
#pragma unroll
            for (int i = 0; i < 8; i++) {
                int idx = t + 512 * i;        // row = idx>>6, col16 = idx&63
                int row = idx >> 6, cc = idx & 63;
                *(float4*)(hdst + row * 520 + cc * 8) = src[idx];
            }
        }
        __syncthreads();
        const int nB = 3 - p;
#pragma unroll
        for (int kk = 0; kk < 4; kk++) {
            int k = ks * 64 + kk * 16;
            uint32_t a[2][4];
#pragma unroll
            for (int mi = 0; mi < 2; mi++)
                ldm_x4(a[mi], hs_u + (uint32_t)(((arow + mi * 16) * 520 + k + acol) * 2));
#pragma unroll
            for (int wb = 0; wb < 3; wb++) {
                if (wb >= nB) break;
                uint32_t Bb = ws_u + (uint32_t)wb * WSPL_B;
                uint32_t bf[2][4];
#pragma unroll
                for (int njp = 0; njp < 2; njp++)
                    ldm_x4(bf[njp], Bb + (uint32_t)(((brow + njp * 16) * 520 + k + bcol) * 2));
#pragma unroll
                for (int mi = 0; mi < 2; mi++) {
                    mma_bf16(c[mi][0], a[mi], bf[0][0], bf[0][1]);
                    mma_bf16(c[mi][1], a[mi], bf[0][2], bf[0][3]);
                    mma_bf16(c[mi][2], a[mi], bf[1][0], bf[1][1]);
                    mma_bf16(c[mi][3], a[mi], bf[1][2], bf[1][3]);
                }
            }
        }
    }
    __syncthreads();                          // h tile dead; A area becomes scratch

    // ---- K-reduction scratch scr[8][64][36] (conflict-light) ----
    float* scr = (float*)(dyn + A_OFF);
#pragma unroll
    for (int mi = 0; mi < 2; mi++)
#pragma unroll
        for (int nj = 0; nj < 4; nj++) {
            int b = mh * 32 + mi * 16 + gid;
            int n = nj * 8 + tid2 * 2;
            scr[ks * 2304 + b * 36 + n]           = c[mi][nj][0];
            scr[ks * 2304 + b * 36 + n + 1]       = c[mi][nj][1];
            scr[ks * 2304 + (b + 8) * 36 + n]     = c[mi][nj][2];
            scr[ks * 2304 + (b + 8) * 36 + n + 1] = c[mi][nj][3];
        }
    __syncthreads();
#pragma unroll
    for (int i = 0; i < 4; i++) {
        int e = t + 512 * i;                  // b = e>>5 (warp-uniform), n = lane
        int b = e >> 5, n = e & 31;
        float s = 0.f;
#pragma unroll
        for (int p = 0; p < 8; p++) s += scr[p * 2304 + b * 36 + n];
        g_u[d][b][cb * 32 + n] = s;
    }
}

// ---------------- fp32 FFMA path for the one-time concat GEMM -----------------
__device__ __forceinline__ void load_Wf(float (*ws)[516], const float* __restrict__ Wbase,
                                        int rowStride, int colOff) {
    int t = threadIdx.x;
#pragma unroll
    for (int i = 0; i < 8; i++) {
        int fi = t + 512 * i;
        int g = fi >> 7, kq = fi & 127;
        *(float4*)&ws[g][kq * 4] =
            *(const float4*)(Wbase + (size_t)g * rowStride + colOff + kq * 4);
    }
}
__device__ __forceinline__ void load_hf(float (*hs)[516], const float* __restrict__ src) {
    int t = threadIdx.x;
#pragma unroll
    for (int i = 0; i < 16; i++) {
        int fi = t + 512 * i;
        int b = fi >> 7, kq = fi & 127;
        *(float4*)&hs[b][kq * 4] = *(const float4*)(src + (size_t)b * HH + kq * 4);
    }
}
__device__ __forceinline__ void gemm_ffma(float (*hs)[516], float (*ws)[516],
                                          float (&acc)[4][2]) {
    int t = threadIdx.x;
    int half = t >> 8;
    int tl = t & 255;
    int tb = tl & 15;
    int tg = tl >> 4;
    const int kk0 = half << 8;
#pragma unroll 4
    for (int k = 0; k < 256; k += 8) {
        float4 w0a = *(const float4*)&ws[2 * tg][kk0 + k];
        float4 w1a = *(const float4*)&ws[2 * tg + 1][kk0 + k];
        float4 w0b = *(const float4*)&ws[2 * tg][kk0 + k + 4];
        float4 w1b = *(const float4*)&ws[2 * tg + 1][kk0 + k + 4];
        float4 ha[4], hb[4];
#pragma unroll
        for (int i = 0; i < 4; i++) {
            ha[i] = *(const float4*)&hs[tb + 16 * i][kk0 + k];
            hb[i] = *(const float4*)&hs[tb + 16 * i][kk0 + k + 4];
        }
#pragma unroll
        for (int i = 0; i < 4; i++) {
            acc[i][0] += ha[i].x * w0a.x + ha[i].y * w0a.y + ha[i].z * w0a.z + ha[i].w * w0a.w;
            acc[i][1] += ha[i].x * w1a.x + ha[i].y * w1a.y + ha[i].z * w1a.z + ha[i].w * w1a.w;
        }
#pragma unroll
        for (int i = 0; i < 4; i++) {
            acc[i][0] += hb[i].x * w0b.x + hb[i].y * w0b.y + hb[i].z * w0b.z + hb[i].w * w0b.w;
            acc[i][1] += hb[i].x * w1b.x + hb[i].y * w1b.y + hb[i].z * w1b.z + hb[i].w * w1b.w;
        }
    }
}
__device__ __forceinline__ void reduce_store_u(float* scratch, int d, int chunk,
                                               float (&acc)[4][2]) {
    int t = threadIdx.x;
    int half = t >> 8;
    int tl = t & 255;
    int tb = tl & 15, tg = tl >> 4;
    __syncthreads();
    if (half == 1) {
#pragma unroll
        for (int i = 0; i < 4; i++) {
            int b = tb + 16 * i;
            scratch[(2 * tg) * 64 + b]     = acc[i][0];
            scratch[(2 * tg + 1) * 64 + b] = acc[i][1];
        }
    }
    __syncthreads();
    if (half == 0) {
#pragma unroll
        for (int i = 0; i < 4; i++) {
            int b = tb + 16 * i;
            float2 o;
            o.x = acc[i][0] + scratch[(2 * tg) * 64 + b];
            o.y = acc[i][1] + scratch[(2 * tg + 1) * 64 + b];
            *(float2*)&g_u[d][b][chunk * 32 + 2 * tg] = o;
        }
    }
}

// ================= pointwise: CTA owns row (d, b); 1 hidden unit per thread ====
__device__ void step_point(int d, int b, const float* gihr, const float* g1row,
                           int useG1, float* red, const float* hhg, const float* hhb,
                           const float* hog, const float* hob, float &c,
                           float* __restrict__ outrow) {
    int j = threadIdx.x;
    const float* urow = &g_u[d][b][0];
    float uv[4], gv4[4];
    float s = 0.f, q = 0.f;
#pragma unroll
    for (int m = 0; m < 4; m++) {
        uv[m] = urow[j + 512 * m];
        s += uv[m]; q += uv[m] * uv[m];
        gv4[m] = useG1 ? g1row[j + 512 * m] : gihr[m];
    }
    float mu, rs;
    block_stats_d(s, q, 1.0f / GG, mu, rs, red);

    float vi = gv4[0] + (uv[0] - mu) * rs * hhg[j]        + hhb[j];
    float vf = gv4[1] + (uv[1] - mu) * rs * hhg[512 + j]  + hhb[512 + j];
    float vo = gv4[2] + (uv[2] - mu) * rs * hhg[1024 + j] + hhb[1024 + j];
    float vg = gv4[3] + (uv[3] - mu) * rs * hhg[1536 + j] + hhb[1536 + j];
    float ig = sigmoidf_(vi);
    float fg = sigmoidf_(vf);
    float og = sigmoidf_(vo);
    float gg = tanhf(vg);
    float cn = fg * c + ig * gg;

    float muc, rsc;
    block_stats_d(cn, cn * cn, 1.0f / HH, muc, rsc, red);
    float hval = og * tanhf((cn - muc) * rsc * hog[j] + hob[j]);
    c = cn;
    g_h[d][b][j] = hval;
    // 3-way bf16 split for next step's tensor GEMM
    __nv_bfloat16 hi = __float2bfloat16(hval);
    float r1 = hval - __bfloat162float(hi);
    __nv_bfloat16 mid = __float2bfloat16(r1);
    float r2 = r1 - __bfloat162float(mid);
    g_hbf[d][0][b][j] = hi;
    g_hbf[d][1][b][j] = mid;
    g_hbf[d][2][b][j] = __float2bfloat16(r2);
    if (outrow) outrow[j] = hval;
}

// layer-1 input LN into smem g1row; reset h (fp32 + bf16) for layer 1
__device__ void g1_finalize(int d, int b, float* g1row, float* red,
                            const float* __restrict__ ihg, const float* __restrict__ ihb) {
    int t = threadIdx.x;
    const float* urow = &g_u[d][b][0];
    float uv[4];
    float s = 0.f, q = 0.f;
#pragma unroll
    for (int m = 0; m < 4; m++) {
        uv[m] = urow[t + 512 * m];
        s += uv[m]; q += uv[m] * uv[m];
    }
    float mu, rs;
    block_stats_d(s, q, 1.0f / GG, mu, rs, red);
#pragma unroll
    for (int m = 0; m < 4; m++) {
        int g = t + 512 * m;
        g1row[g] = (uv[m] - mu) * rs * ihg[g] + ihb[g];
    }
    g_h[d][b][t] = 0.f;
    g_hbf[d][0][b][t] = __float2bfloat16(0.f);
    g_hbf[d][1][b][t] = __float2bfloat16(0.f);
    g_hbf[d][2][b][t] = __float2bfloat16(0.f);
}

__device__ void load_params(float* hhg, float* hhb, float* hog, float* hob,
                            const float* shhg, const float* shhb,
                            const float* shog, const float* shob) {
    int t = threadIdx.x;
#pragma unroll
    for (int i = 0; i < 4; i++) {
        int j = t + 512 * i;
        hhg[j] = shhg[j];
        hhb[j] = shhb[j];
    }
    hog[t] = shog[t];
    hob[t] = shob[t];
}

// ================= persistent recurrent kernel ================================
__global__ void __launch_bounds__(512, 1) scan_kernel(
    const float* __restrict__ w_hh0,
    const float* __restrict__ ln_hh0_g, const float* __restrict__ ln_hh0_b,
    const float* __restrict__ ln_ho0_g, const float* __restrict__ ln_ho0_b,
    const float* __restrict__ w_ih1, const float* __restrict__ w_hh1,
    const float* __restrict__ ln_ih1_g, const float* __restrict__ ln_ih1_b,
    const float* __restrict__ ln_hh1_g, const float* __restrict__ ln_hh1_b,
    const float* __restrict__ ln_ho1_g, const float* __restrict__ ln_ho1_b,
    float* __restrict__ out) {
    extern __shared__ unsigned char dynbuf[];
    uint32_t base_u = smem_u32(dynbuf);
    float* red = (float*)dynbuf;
    float* P = (float*)(dynbuf + P_OFF);
    float* hhg = P;
    float* hhb = P + 2048;
    float* hog = P + 4096;
    float* hob = P + 4608;
    float* g1row = P + 5120;

    int r = blockIdx.x;
    int d = r >> 6;
    int cb = r & 63;
    int t = threadIdx.x;
    unsigned target = 0;
    float c = 0.f;

    // one-time setup: resident layer-0 W (bf16 3-way split), params, zero states
    loadW_bf16(dynbuf, w_hh0 + ((size_t)d * GG + cb * 32) * HH);
    load_params(hhg, hhb, hog, hob, ln_hh0_g + d * GG, ln_hh0_b + d * GG,
                ln_ho0_g + d * HH, ln_ho0_b + d * HH);
    g_h[d][cb][t] = 0.f;
    g_hbf[d][0][cb][t] = __float2bfloat16(0.f);
    g_hbf[d][1][cb][t] = __float2bfloat16(0.f);
    g_hbf[d][2][cb][t] = __float2bfloat16(0.f);
    grid_sync(target);

    // ---- layer 0 scan ----
    for (int st = 0; st < SS; st++) {
        int te = (d == 0) ? st : (SS - 1 - st);
        const float* gptr = &g_gih0[d][te][cb][0];
        float gihr[4];
#pragma unroll
        for (int m = 0; m < 4; m++) gihr[m] = gptr[t + 512 * m];
        step_gemm_mma(d, cb, dynbuf, base_u);
        grid_sync(target);
        step_point(d, cb, gihr, g1row, 0, red, hhg, hhb, hog, hob, c, nullptr);
        grid_sync(target);
    }

    // ---- layer-1 input: u = concat(hf,hb) @ W_ih1^T (one-time FFMA path) ----
    {
        float (*hsf)[516] = (float (*)[516])(dynbuf + A_OFF);
        float (*wsf)[516] = (float (*)[516])(dynbuf + CW_OFF);
        float acc[4][2];
#pragma unroll
        for (int i = 0; i < 4; i++) { acc[i][0] = 0.f; acc[i][1] = 0.f; }
        load_Wf(wsf, w_ih1 + ((size_t)d * GG + cb * 32) * (2 * HH), 2 * HH, 0);
        load_hf(hsf, &g_h[0][0][0]);
        __syncthreads();
        gemm_ffma(hsf, wsf, acc);
        __syncthreads();
        load_Wf(wsf, w_ih1 + ((size_t)d * GG + cb * 32) * (2 * HH), 2 * HH, HH);
        load_hf(hsf, &g_h[1][0][0]);
        __syncthreads();
        gemm_ffma(hsf, wsf, acc);
        reduce_store_u((float*)(dynbuf + A_OFF), d, cb, acc);
    }
    grid_sync(target);
    g1_finalize(d, cb, g1row, red, ln_ih1_g + d * GG, ln_ih1_b + d * GG);
    c = 0.f;
    __syncthreads();
    // rebuild tensor-GEMM state for layer 1
    loadW_bf16(dynbuf, w_hh1 + ((size_t)d * GG + cb * 32) * HH);
    load_params(hhg, hhb, hog, hob, ln_hh1_g + d * GG, ln_hh1_b + d * GG,
                ln_ho1_g + d * HH, ln_ho1_b + d * HH);
    grid_sync(target);

    // ---- layer 1 scan (time-constant input in g1row) ----
    for (int st = 0; st < SS; st++) {
        step_gemm_mma(d, cb, dynbuf, base_u);
        grid_sync(target);
        bool last = (st == SS - 1);
        step_point(d, cb, nullptr, g1row, 1, red, hhg, hhb, hog, hob, c,
                   last ? (out + (size_t)cb * 1024 + d * 512) : nullptr);
        if (!last) grid_sync(target);
    }

    // ---- exit protocol: last CTA to leave resets barrier counters ----
    __syncthreads();
    if (t == 0) {
        __threadfence();
        unsigned n = atomicAdd(&g_excnt, 1u) + 1;
        if (n == NCTA) {
            g_barcnt = 0;
            g_excnt = 0;
            __threadfence();
        }
    }
}

// =============================================================================
extern "C" void kernel_launch(void* const* d_in, const int* in_sizes, int n_in,
                              void* d_out, int out_size) {
    const float* x        = (const float*)d_in[0];
    // d_in[1] = text_length (unused by the reference forward)
    const float* w_ih0    = (const float*)d_in[2];
    const float* w_hh0    = (const float*)d_in[3];
    const float* ln_ih0_g = (const float*)d_in[4];
    const float* ln_ih0_b = (const float*)d_in[5];
    const float* ln_hh0_g = (const float*)d_in[6];
    const float* ln_hh0_b = (const float*)d_in[7];
    const float* ln_ho0_g = (const float*)d_in[8];
    const float* ln_ho0_b = (const float*)d_in[9];
    const float* w_ih1    = (const float*)d_in[10];
    const float* w_hh1    = (const float*)d_in[11];
    const float* ln_ih1_g = (const float*)d_in[12];
    const float* ln_ih1_b = (const float*)d_in[13];
    const float* ln_hh1_g = (const float*)d_in[14];
    const float* ln_hh1_b = (const float*)d_in[15];
    const float* ln_ho1_g = (const float*)d_in[16];
    const float* ln_ho1_b = (const float*)d_in[17];
    float* out = (float*)d_out;

    static int smem_set = 0;
    if (!smem_set) {
        cudaFuncSetAttribute(scan_kernel, cudaFuncAttributeMaxDynamicSharedMemorySize,
                             SCAN_SMEM_BYTES);
        smem_set = 1;
    }

    phaseA_gemm<<<2 * SS * 32, 256>>>(x, w_ih0);
    phaseA_ln<<<2 * SS * BB, 256>>>(ln_ih0_g, ln_ih0_b);
    scan_kernel<<<NCTA, 512, SCAN_SMEM_BYTES>>>(
        w_hh0, ln_hh0_g, ln_hh0_b, ln_ho0_g, ln_ho0_b,
        w_ih1, w_hh1, ln_ih1_g, ln_ih1_b,
        ln_hh1_g, ln_hh1_b, ln_ho1_g, ln_ho1_b, out);
}